// round 13
// baseline (speedup 1.0000x reference)
#include <cuda_runtime.h>
#include <cuda_bf16.h>
#include <cstdint>
#include <stdint.h>
#include <math.h>

#define NN 50000
#define EE 800000
#define HH 128
#define HP 64           // bf16 pairs per 128-wide row
#define M3 (3*HH)       // 384
#define SCAN_BLOCKS ((NN + 1023) / 1024)   // 49

// ---------------- scratch (static __device__, no allocation) ----------------
__device__ float g_h [NN*HH];
__device__ float g_h2[NN*HH];
__device__ float g_gi[NN*M3];
__device__ float g_gh[NN*M3];
__device__ float g_wcf0[HH*M3];     // Wc0 = W_msg0 @ wih0^T (fp32)
__device__ float g_wcf1[HH*M3];
__device__ uint2 g_xpk  [NN*HP];
__device__ uint2 g_hpk  [NN*HP];
__device__ uint2 g_aggpk[NN*HP];
__device__ uint2 g_wpk_in[HH*HP];
__device__ uint2 g_wpk_c0[M3*HP];   // packed Wc0
__device__ uint2 g_wpk_c1[M3*HP];
__device__ uint2 g_wpk_h0[M3*HP];
__device__ uint2 g_wpk_h1[M3*HP];
__device__ int   g_deg [NN];
__device__ int   g_off [NN + 1];
__device__ int   g_cur [NN];
__device__ int   g_srcs[EE];
__device__ int   g_blk [64];
__device__ int   g_blkoff[64];

// ---------------- bf16 hi/lo packing helpers ----------------
__device__ __forceinline__ uint32_t pack2(float v0, float v1) {
    uint32_t r;
    asm("cvt.rn.bf16x2.f32 %0, %1, %2;" : "=r"(r) : "f"(v1), "f"(v0));
    return r;
}

__device__ __forceinline__ uint2 pack_hilo(float v0, float v1) {
    uint32_t hi = pack2(v0, v1);
    float h0 = __uint_as_float(hi << 16);
    float h1 = __uint_as_float(hi & 0xffff0000u);
    uint32_t lo = pack2(v0 - h0, v1 - h1);
    return make_uint2(hi, lo);
}

// ---------------- Wc = W_msg @ wih^T  (fp32, [128 k][384 n] row-major) ----------------
__global__ void wc_compute(const float* __restrict__ Wm, const float* __restrict__ wih,
                           float* __restrict__ out) {
    int idx = blockIdx.x * blockDim.x + threadIdx.x;
    if (idx >= HH * M3) return;
    int k = idx / M3;
    int n = idx - k * M3;
    float s = 0.0f;
    #pragma unroll 8
    for (int j = 0; j < HH; j++) s += Wm[k * HH + j] * wih[n * HH + j];
    out[idx] = s;
}

// ---------------- generic B packer (used for Wc fp32 -> packed) ----------------
// trans=0: B given as [128 k][M n] row-major; trans=1: [M n][128 k]
__global__ void pack_B(const float* __restrict__ W, uint2* __restrict__ out,
                       int M, int trans) {
    int idx = blockIdx.x * blockDim.x + threadIdx.x;
    if (idx >= M * HP) return;
    int n = idx / HP;
    int p = idx - n * HP;
    float v0, v1;
    if (trans) { v0 = W[n * HH + 2 * p];  v1 = W[n * HH + 2 * p + 1]; }
    else       { v0 = W[(2 * p) * M + n]; v1 = W[(2 * p + 1) * M + n]; }
    out[idx] = pack_hilo(v0, v1);
}

// ---------------- fused weight packer (W_in, whh0, whh1) ----------------
__global__ void pack_all3(const float* __restrict__ W_in,
                          const float* __restrict__ whh0, const float* __restrict__ whh1) {
    int idx = blockIdx.x * blockDim.x + threadIdx.x;
    const float* W; uint2* out; int M; int trans; int base;
    if      (idx <  8192) { W = W_in; out = g_wpk_in; M = HH; trans = 0; base = 0; }
    else if (idx < 32768) { W = whh0; out = g_wpk_h0; M = M3; trans = 1; base = 8192; }
    else if (idx < 57344) { W = whh1; out = g_wpk_h1; M = M3; trans = 1; base = 32768; }
    else return;
    int li = idx - base;
    int n = li / HP;
    int p = li - n * HP;
    float v0, v1;
    if (trans) { v0 = W[n * HH + 2 * p];  v1 = W[n * HH + 2 * p + 1]; }
    else       { v0 = W[(2 * p) * M + n]; v1 = W[(2 * p + 1) * M + n]; }
    out[li] = pack_hilo(v0, v1);
}

__global__ void pack_A(const float* __restrict__ A, uint2* __restrict__ out, int rows) {
    int idx = blockIdx.x * blockDim.x + threadIdx.x;
    if (idx >= rows * HP) return;
    int r = idx >> 6;
    int p = idx & 63;
    float2 v = *(const float2*)(A + (size_t)r * HH + 2 * p);
    out[idx] = pack_hilo(v.x, v.y);
}

// ---------------- CSR build ----------------
__global__ void count_deg(const int* __restrict__ dst) {
    int e = blockIdx.x * blockDim.x + threadIdx.x;
    if (e < EE) atomicAdd(&g_deg[dst[e]], 1);
}

__global__ void scan_local() {
    int b = blockIdx.x;
    int i = b * 1024 + threadIdx.x;
    int lane = threadIdx.x & 31, wid = threadIdx.x >> 5;
    int v = (i < NN) ? g_deg[i] : 0;
    int x = v;
    #pragma unroll
    for (int o = 1; o < 32; o <<= 1) {
        int t = __shfl_up_sync(0xffffffffu, x, o);
        if (lane >= o) x += t;
    }
    __shared__ int wsum[32];
    if (lane == 31) wsum[wid] = x;
    __syncthreads();
    if (wid == 0) {
        int y = wsum[lane];
        #pragma unroll
        for (int o = 1; o < 32; o <<= 1) {
            int t = __shfl_up_sync(0xffffffffu, y, o);
            if (lane >= o) y += t;
        }
        wsum[lane] = y;
    }
    __syncthreads();
    int excl = x - v + (wid > 0 ? wsum[wid - 1] : 0);
    if (i < NN) g_off[i] = excl;
    if (threadIdx.x == 1023) g_blk[b] = excl + v;
}

__global__ void scan_blk() {
    if (threadIdx.x == 0) {
        int s = 0;
        for (int i = 0; i < SCAN_BLOCKS; i++) {
            int t = g_blk[i];
            g_blkoff[i] = s;
            s += t;
        }
        g_off[NN] = s;
    }
}

__global__ void scan_add() {
    int i = blockIdx.x * blockDim.x + threadIdx.x;
    if (i < NN) {
        int o = g_off[i] + g_blkoff[i >> 10];
        g_off[i] = o;
        g_cur[i] = o;
    }
}

__global__ void scatter_edges(const int* __restrict__ src, const int* __restrict__ dst) {
    int e = blockIdx.x * blockDim.x + threadIdx.x;
    if (e < EE) {
        int p = atomicAdd(&g_cur[dst[e]], 1);
        g_srcs[p] = src[e];
    }
}

// ---------------- cp.async helper ----------------
__device__ __forceinline__ void cp16(void* smem_dst, const void* gsrc, bool valid) {
    uint32_t saddr = (uint32_t)__cvta_generic_to_shared(smem_dst);
    int sz = valid ? 16 : 0;
    asm volatile("cp.async.cg.shared.global [%0], [%1], 16, %2;\n"
                 :: "r"(saddr), "l"(gsrc), "r"(sz));
}

// ---------------- bf16x2 split-MMA GEMM (tile 128x64, 2 blocks/SM) ----------------
__device__ __forceinline__ void mma_bf16(float* d, const uint32_t* a, const uint32_t* b) {
    asm volatile(
        "mma.sync.aligned.m16n8k16.row.col.f32.bf16.bf16.f32 "
        "{%0,%1,%2,%3}, {%4,%5,%6,%7}, {%8,%9}, {%0,%1,%2,%3};"
        : "+f"(d[0]), "+f"(d[1]), "+f"(d[2]), "+f"(d[3])
        : "r"(a[0]), "r"(a[1]), "r"(a[2]), "r"(a[3]), "r"(b[0]), "r"(b[1]));
}

#define ASTRIDE 68
#define GEMM_SMEM ((128 + 64) * ASTRIDE * 8)

__global__ void __launch_bounds__(256, 2)
bf16x2_gemm(const uint2* __restrict__ Apk, const uint2* __restrict__ Bpk,
            const float* __restrict__ bias, float* __restrict__ C,
            uint2* __restrict__ Cpk, int nrows, int M, int relu) {
    extern __shared__ uint2 sm[];
    uint2* As = sm;
    uint2* Bs = sm + 128 * ASTRIDE;
    int tid  = threadIdx.x;
    int wid  = tid >> 5, lane = tid & 31;
    int gid  = lane >> 2, tg = lane & 3;
    int wm   = (wid & 3) * 32;
    int wn   = (wid >> 2) * 32;
    int r0   = blockIdx.y * 128;
    int n0   = blockIdx.x * 64;

    #pragma unroll
    for (int t = 0; t < 16; t++) {
        int q   = tid + t * 256;
        int row = q >> 5;
        int j   = q & 31;
        bool ok = (r0 + row < nrows);
        cp16(As + row * ASTRIDE + 2 * j,
             Apk + (size_t)(r0 + row) * HP + 2 * j, ok);
    }
    #pragma unroll
    for (int t = 0; t < 8; t++) {
        int q   = tid + t * 256;
        int col = q >> 5;
        int j   = q & 31;
        cp16(Bs + col * ASTRIDE + 2 * j,
             Bpk + (size_t)(n0 + col) * HP + 2 * j, true);
    }
    asm volatile("cp.async.commit_group;\n");
    asm volatile("cp.async.wait_group 0;\n");
    __syncthreads();

    float acc[2][4][4];
    #pragma unroll
    for (int mt = 0; mt < 2; mt++)
        #pragma unroll
        for (int nt = 0; nt < 4; nt++)
            #pragma unroll
            for (int k = 0; k < 4; k++) acc[mt][nt][k] = 0.0f;

    #pragma unroll
    for (int s = 0; s < 8; s++) {
        int p0 = 8 * s;
        uint32_t ah[2][4], al[2][4];
        #pragma unroll
        for (int mt = 0; mt < 2; mt++) {
            int r = wm + mt * 16 + gid;
            uint2 u0 = As[r * ASTRIDE + p0 + tg];
            uint2 u1 = As[(r + 8) * ASTRIDE + p0 + tg];
            uint2 u2 = As[r * ASTRIDE + p0 + tg + 4];
            uint2 u3 = As[(r + 8) * ASTRIDE + p0 + tg + 4];
            ah[mt][0] = u0.x; ah[mt][1] = u1.x; ah[mt][2] = u2.x; ah[mt][3] = u3.x;
            al[mt][0] = u0.y; al[mt][1] = u1.y; al[mt][2] = u2.y; al[mt][3] = u3.y;
        }
        #pragma unroll
        for (int nt = 0; nt < 4; nt++) {
            int c = wn + nt * 8 + gid;
            uint2 v0 = Bs[c * ASTRIDE + p0 + tg];
            uint2 v1 = Bs[c * ASTRIDE + p0 + tg + 4];
            uint32_t bh[2] = { v0.x, v1.x };
            uint32_t bl[2] = { v0.y, v1.y };
            #pragma unroll
            for (int mt = 0; mt < 2; mt++) {
                mma_bf16(acc[mt][nt], ah[mt], bh);
                mma_bf16(acc[mt][nt], al[mt], bh);
                mma_bf16(acc[mt][nt], ah[mt], bl);
            }
        }
    }

    #pragma unroll
    for (int nt = 0; nt < 4; nt++) {
        int c = n0 + wn + nt * 8 + 2 * tg;
        float b0 = bias ? bias[c] : 0.0f;
        float b1 = bias ? bias[c + 1] : 0.0f;
        #pragma unroll
        for (int mt = 0; mt < 2; mt++) {
            int row = r0 + wm + mt * 16 + gid;
            float v0 = acc[mt][nt][0] + b0;
            float v1 = acc[mt][nt][1] + b1;
            float v2 = acc[mt][nt][2] + b0;
            float v3 = acc[mt][nt][3] + b1;
            if (relu) {
                v0 = fmaxf(v0, 0.0f); v1 = fmaxf(v1, 0.0f);
                v2 = fmaxf(v2, 0.0f); v3 = fmaxf(v3, 0.0f);
            }
            if (row < nrows) {
                *(float2*)(C + (size_t)row * M + c) = make_float2(v0, v1);
                if (Cpk) Cpk[(size_t)row * HP + (c >> 1)] = pack_hilo(v0, v1);
            }
            if (row + 8 < nrows) {
                *(float2*)(C + (size_t)(row + 8) * M + c) = make_float2(v2, v3);
                if (Cpk) Cpk[(size_t)(row + 8) * HP + (c >> 1)] = pack_hilo(v2, v3);
            }
        }
    }
}

// ---------------- gather-sum over node features (CSR) -> packed agg ----------------
__global__ void gather_sum(const float* __restrict__ hsrc, uint2* __restrict__ aggpk) {
    int w    = (blockIdx.x * blockDim.x + threadIdx.x) >> 5;
    int lane = threadIdx.x & 31;
    if (w >= NN) return;
    int s0 = g_off[w], s1 = g_off[w + 1];
    float4 acc = make_float4(0.f, 0.f, 0.f, 0.f);
    for (int e = s0; e < s1; e++) {
        int s = g_srcs[e];
        float4 v = *((const float4*)(hsrc + (size_t)s * HH) + lane);
        acc.x += v.x; acc.y += v.y; acc.z += v.z; acc.w += v.w;
    }
    uint2 p0 = pack_hilo(acc.x, acc.y);
    uint2 p1 = pack_hilo(acc.z, acc.w);
    *(uint4*)(aggpk + (size_t)w * HP + 2 * lane) = make_uint4(p0.x, p0.y, p1.x, p1.y);
}

// ---------------- GRU elementwise update ----------------
__device__ __forceinline__ float sigm(float x) { return 1.0f / (1.0f + __expf(-x)); }

__global__ void gru_update(const float* __restrict__ gi, const float* __restrict__ gh,
                           const float* __restrict__ h, float* __restrict__ hout,
                           uint2* __restrict__ pk) {
    int tid = blockIdx.x * blockDim.x + threadIdx.x;
    if (tid >= NN * 32) return;
    int n = tid >> 5;
    int j = tid & 31;
    const float4* gir = (const float4*)(gi + (size_t)n * M3);
    const float4* ghr = (const float4*)(gh + (size_t)n * M3);
    float4 ir  = gir[j],      iz  = gir[32 + j], inn = gir[64 + j];
    float4 hr  = ghr[j],      hz  = ghr[32 + j], hn  = ghr[64 + j];
    float4 hv  = *((const float4*)(h + (size_t)n * HH) + j);
    float4 o;
    {
        float rt = sigm(ir.x + hr.x), zt = sigm(iz.x + hz.x);
        float nt = tanhf(inn.x + rt * hn.x);
        o.x = (1.0f - zt) * nt + zt * hv.x;
    }
    {
        float rt = sigm(ir.y + hr.y), zt = sigm(iz.y + hz.y);
        float nt = tanhf(inn.y + rt * hn.y);
        o.y = (1.0f - zt) * nt + zt * hv.y;
    }
    {
        float rt = sigm(ir.z + hr.z), zt = sigm(iz.z + hz.z);
        float nt = tanhf(inn.z + rt * hn.z);
        o.z = (1.0f - zt) * nt + zt * hv.z;
    }
    {
        float rt = sigm(ir.w + hr.w), zt = sigm(iz.w + hz.w);
        float nt = tanhf(inn.w + rt * hn.w);
        o.w = (1.0f - zt) * nt + zt * hv.w;
    }
    *((float4*)(hout + (size_t)n * HH) + j) = o;
    if (pk) {
        uint2 p0 = pack_hilo(o.x, o.y);
        uint2 p1 = pack_hilo(o.z, o.w);
        *(uint4*)(pk + (size_t)n * HP + 2 * j) = make_uint4(p0.x, p0.y, p1.x, p1.y);
    }
}

// ---------------- final projection (fp32, small: M=32) ----------------
__global__ void sgemm_bias(const float* __restrict__ A, const float* __restrict__ B,
                           const float* __restrict__ bias, float* __restrict__ C,
                           int nrows, int M, int relu) {
    __shared__ float As[64][65];
    __shared__ float Bs[64][65];
    int tx = threadIdx.x, ty = threadIdx.y;
    int tid = ty * 16 + tx;
    int r0 = blockIdx.y * 64;
    int n0 = blockIdx.x * 64;

    float acc[4][4];
    #pragma unroll
    for (int i = 0; i < 4; i++)
        #pragma unroll
        for (int j = 0; j < 4; j++) acc[i][j] = 0.0f;

    for (int kk = 0; kk < 128; kk += 64) {
        #pragma unroll
        for (int t = 0; t < 4; t++) {
            int q = tid + t * 256;
            int row = q >> 4;
            int c4  = q & 15;
            float4 v = make_float4(0.f, 0.f, 0.f, 0.f);
            int gr = r0 + row;
            if (gr < nrows) v = *(const float4*)(A + (size_t)gr * 128 + kk + c4 * 4);
            As[row][c4 * 4 + 0] = v.x; As[row][c4 * 4 + 1] = v.y;
            As[row][c4 * 4 + 2] = v.z; As[row][c4 * 4 + 3] = v.w;
        }
        #pragma unroll
        for (int t = 0; t < 4; t++) {
            int q = tid + t * 256;
            int brow = q >> 4;
            int c4   = q & 15;
            float4 v = make_float4(0.f, 0.f, 0.f, 0.f);
            int gc = n0 + c4 * 4;
            if (gc < M) v = *(const float4*)(B + (size_t)(kk + brow) * M + gc);
            Bs[brow][c4 * 4 + 0] = v.x; Bs[brow][c4 * 4 + 1] = v.y;
            Bs[brow][c4 * 4 + 2] = v.z; Bs[brow][c4 * 4 + 3] = v.w;
        }
        __syncthreads();
        #pragma unroll
        for (int k = 0; k < 64; k++) {
            float a0 = As[ty * 4 + 0][k], a1 = As[ty * 4 + 1][k];
            float a2 = As[ty * 4 + 2][k], a3 = As[ty * 4 + 3][k];
            float b0 = Bs[k][tx * 4 + 0], b1 = Bs[k][tx * 4 + 1];
            float b2 = Bs[k][tx * 4 + 2], b3 = Bs[k][tx * 4 + 3];
            acc[0][0] += a0 * b0; acc[0][1] += a0 * b1; acc[0][2] += a0 * b2; acc[0][3] += a0 * b3;
            acc[1][0] += a1 * b0; acc[1][1] += a1 * b1; acc[1][2] += a1 * b2; acc[1][3] += a1 * b3;
            acc[2][0] += a2 * b0; acc[2][1] += a2 * b1; acc[2][2] += a2 * b2; acc[2][3] += a2 * b3;
            acc[3][0] += a3 * b0; acc[3][1] += a3 * b1; acc[3][2] += a3 * b2; acc[3][3] += a3 * b3;
        }
        __syncthreads();
    }

    #pragma unroll
    for (int i = 0; i < 4; i++) {
        int gr = r0 + ty * 4 + i;
        if (gr >= nrows) continue;
        #pragma unroll
        for (int j = 0; j < 4; j++) {
            int gc = n0 + tx * 4 + j;
            if (gc >= M) continue;
            float v = acc[i][j] + (bias ? bias[gc] : 0.0f);
            if (relu) v = fmaxf(v, 0.0f);
            C[(size_t)gr * M + gc] = v;
        }
    }
}

// ---------------- cached streams/events (created once, before graph capture) ----------------
static cudaStream_t sCsr = nullptr, s2 = nullptr;
static cudaEvent_t ev0, evCsr, evWc, evH0, evGh0, evH1, evGh1;
static bool g_res_init = false;

static void init_resources_once() {
    if (g_res_init) return;
    cudaStreamCreateWithFlags(&sCsr, cudaStreamNonBlocking);
    cudaStreamCreateWithFlags(&s2,   cudaStreamNonBlocking);
    cudaEventCreateWithFlags(&ev0,   cudaEventDisableTiming);
    cudaEventCreateWithFlags(&evCsr, cudaEventDisableTiming);
    cudaEventCreateWithFlags(&evWc,  cudaEventDisableTiming);
    cudaEventCreateWithFlags(&evH0,  cudaEventDisableTiming);
    cudaEventCreateWithFlags(&evGh0, cudaEventDisableTiming);
    cudaEventCreateWithFlags(&evH1,  cudaEventDisableTiming);
    cudaEventCreateWithFlags(&evGh1, cudaEventDisableTiming);
    g_res_init = true;
}

// ---------------- launch (forked-stream graph) ----------------
extern "C" void kernel_launch(void* const* d_in, const int* in_sizes, int n_in,
                              void* d_out, int out_size) {
    const float* x      = (const float*)d_in[0];
    const int*   ei     = (const int*)  d_in[1];
    const float* W_in   = (const float*)d_in[2];
    const float* b_in   = (const float*)d_in[3];
    const float* W_msg0 = (const float*)d_in[4];
    const float* wih0   = (const float*)d_in[5];
    const float* whh0   = (const float*)d_in[6];
    const float* bih0   = (const float*)d_in[7];
    const float* bhh0   = (const float*)d_in[8];
    const float* W_msg1 = (const float*)d_in[9];
    const float* wih1   = (const float*)d_in[10];
    const float* whh1   = (const float*)d_in[11];
    const float* bih1   = (const float*)d_in[12];
    const float* bhh1   = (const float*)d_in[13];
    const float* W_out  = (const float*)d_in[14];
    const float* b_out  = (const float*)d_in[15];
    float* out = (float*)d_out;

    const int* src = ei;
    const int* dst = ei + EE;

    float *h, *h2, *gi, *gh, *wcf0, *wcf1;
    uint2 *xpk, *hpk, *aggpk, *win, *wc0, *wc1, *wh0, *wh1;
    int* deg;
    cudaGetSymbolAddress((void**)&h,     g_h);
    cudaGetSymbolAddress((void**)&h2,    g_h2);
    cudaGetSymbolAddress((void**)&gi,    g_gi);
    cudaGetSymbolAddress((void**)&gh,    g_gh);
    cudaGetSymbolAddress((void**)&wcf0,  g_wcf0);
    cudaGetSymbolAddress((void**)&wcf1,  g_wcf1);
    cudaGetSymbolAddress((void**)&xpk,   g_xpk);
    cudaGetSymbolAddress((void**)&hpk,   g_hpk);
    cudaGetSymbolAddress((void**)&aggpk, g_aggpk);
    cudaGetSymbolAddress((void**)&win,   g_wpk_in);
    cudaGetSymbolAddress((void**)&wc0,   g_wpk_c0);
    cudaGetSymbolAddress((void**)&wc1,   g_wpk_c1);
    cudaGetSymbolAddress((void**)&wh0,   g_wpk_h0);
    cudaGetSymbolAddress((void**)&wh1,   g_wpk_h1);
    cudaGetSymbolAddress((void**)&deg,   g_deg);

    cudaFuncSetAttribute(bf16x2_gemm, cudaFuncAttributeMaxDynamicSharedMemorySize, GEMM_SMEM);

    init_resources_once();

    int rb = (NN + 127) / 128;
    int gthreads = NN * 32;

    // ---- fork: CSR build on sCsr (depends only on edge_index) ----
    cudaEventRecord(ev0, 0);
    cudaStreamWaitEvent(sCsr, ev0, 0);
    cudaMemsetAsync(deg, 0, NN * sizeof(int), sCsr);
    count_deg<<<(EE + 255) / 256, 256, 0, sCsr>>>(dst);
    scan_local<<<SCAN_BLOCKS, 1024, 0, sCsr>>>();
    scan_blk<<<1, 32, 0, sCsr>>>();
    scan_add<<<SCAN_BLOCKS, 1024, 0, sCsr>>>();
    scatter_edges<<<(EE + 255) / 256, 256, 0, sCsr>>>(src, dst);
    cudaEventRecord(evCsr, sCsr);

    // ---- fork: Wc prep on s2 (depends only on weights) ----
    cudaStreamWaitEvent(s2, ev0, 0);
    wc_compute<<<(HH * M3 + 255) / 256, 256, 0, s2>>>(W_msg0, wih0, wcf0);
    pack_B<<<(M3 * HP + 255) / 256, 256, 0, s2>>>(wcf0, wc0, M3, 0);
    wc_compute<<<(HH * M3 + 255) / 256, 256, 0, s2>>>(W_msg1, wih1, wcf1);
    pack_B<<<(M3 * HP + 255) / 256, 256, 0, s2>>>(wcf1, wc1, M3, 0);
    cudaEventRecord(evWc, s2);

    // ---- main stream: pack + input GEMM ----
    pack_all3<<<(57344 + 255) / 256, 256>>>(W_in, whh0, whh1);
    pack_A<<<(NN * HP + 255) / 256, 256>>>(x, xpk, NN);
    bf16x2_gemm<<<dim3(2, rb), 256, GEMM_SMEM>>>(xpk, win, b_in, h, hpk, NN, HH, 1);
    cudaEventRecord(evH0, 0);

    // ---- layer 0: gh on s2, gather->gi on main ----
    cudaStreamWaitEvent(s2, evH0, 0);
    bf16x2_gemm<<<dim3(6, rb), 256, GEMM_SMEM, s2>>>(hpk, wh0, bhh0, gh, nullptr, NN, M3, 0);
    cudaEventRecord(evGh0, s2);

    cudaStreamWaitEvent(0, evCsr, 0);
    gather_sum<<<(gthreads + 255) / 256, 256>>>(h, aggpk);
    cudaStreamWaitEvent(0, evWc, 0);
    bf16x2_gemm<<<dim3(6, rb), 256, GEMM_SMEM>>>(aggpk, wc0, bih0, gi, nullptr, NN, M3, 0);
    cudaStreamWaitEvent(0, evGh0, 0);
    gru_update<<<(gthreads + 255) / 256, 256>>>(gi, gh, h, h2, hpk);
    cudaEventRecord(evH1, 0);

    // ---- layer 1: gh on s2, gather->gi on main ----
    cudaStreamWaitEvent(s2, evH1, 0);
    bf16x2_gemm<<<dim3(6, rb), 256, GEMM_SMEM, s2>>>(hpk, wh1, bhh1, gh, nullptr, NN, M3, 0);
    cudaEventRecord(evGh1, s2);

    gather_sum<<<(gthreads + 255) / 256, 256>>>(h2, aggpk);
    bf16x2_gemm<<<dim3(6, rb), 256, GEMM_SMEM>>>(aggpk, wc1, bih1, gi, nullptr, NN, M3, 0);
    cudaStreamWaitEvent(0, evGh1, 0);
    gru_update<<<(gthreads + 255) / 256, 256>>>(gi, gh, h2, h, nullptr);

    // out = h @ W_out + b_out
    sgemm_bias<<<dim3(1, (NN + 63) / 64), dim3(16, 16)>>>(h, W_out, b_out, out, NN, 32, 0);
}

// round 14
// speedup vs baseline: 1.0264x; 1.0264x over previous
#include <cuda_runtime.h>
#include <cuda_bf16.h>
#include <cstdint>
#include <stdint.h>
#include <math.h>

#define NN 50000
#define EE 800000
#define HH 128
#define HP 64           // bf16 pairs per 128-wide row
#define M3 (3*HH)       // 384
#define SCAN_BLOCKS ((NN + 1023) / 1024)   // 49

// ---------------- scratch (static __device__, no allocation) ----------------
__device__ float g_h [NN*HH];
__device__ float g_h2[NN*HH];
__device__ float g_gi[NN*M3];
__device__ float g_gh[NN*M3];
__device__ float g_wcf0[HH*M3];     // Wc0 = W_msg0 @ wih0^T (fp32)
__device__ float g_wcf1[HH*M3];
__device__ uint2 g_xpk  [NN*HP];
__device__ uint2 g_hpk  [NN*HP];
__device__ uint2 g_aggpk[NN*HP];
__device__ uint2 g_wpk_in[HH*HP];
__device__ uint2 g_wpk_c0[M3*HP];   // packed Wc0
__device__ uint2 g_wpk_c1[M3*HP];
__device__ uint2 g_wpk_h0[M3*HP];
__device__ uint2 g_wpk_h1[M3*HP];
__device__ uint2 g_wpk_out[64*HP];  // packed W_out (zero-padded to 64 cols)
__device__ int   g_deg [NN];
__device__ int   g_off [NN + 1];
__device__ int   g_cur [NN];
__device__ int   g_srcs[EE];
__device__ int   g_blk [64];
__device__ int   g_blkoff[64];

// ---------------- bf16 hi/lo packing helpers ----------------
__device__ __forceinline__ uint32_t pack2(float v0, float v1) {
    uint32_t r;
    asm("cvt.rn.bf16x2.f32 %0, %1, %2;" : "=r"(r) : "f"(v1), "f"(v0));
    return r;
}

__device__ __forceinline__ uint2 pack_hilo(float v0, float v1) {
    uint32_t hi = pack2(v0, v1);
    float h0 = __uint_as_float(hi << 16);
    float h1 = __uint_as_float(hi & 0xffff0000u);
    uint32_t lo = pack2(v0 - h0, v1 - h1);
    return make_uint2(hi, lo);
}

// ---------------- Wc = W_msg @ wih^T  (fp32, [128 k][384 n] row-major) ----------------
__global__ void wc_compute(const float* __restrict__ Wm, const float* __restrict__ wih,
                           float* __restrict__ out) {
    int idx = blockIdx.x * blockDim.x + threadIdx.x;
    if (idx >= HH * M3) return;
    int k = idx / M3;
    int n = idx - k * M3;
    float s = 0.0f;
    #pragma unroll 8
    for (int j = 0; j < HH; j++) s += Wm[k * HH + j] * wih[n * HH + j];
    out[idx] = s;
}

// ---------------- generic B packer ----------------
__global__ void pack_B(const float* __restrict__ W, uint2* __restrict__ out,
                       int M, int trans) {
    int idx = blockIdx.x * blockDim.x + threadIdx.x;
    if (idx >= M * HP) return;
    int n = idx / HP;
    int p = idx - n * HP;
    float v0, v1;
    if (trans) { v0 = W[n * HH + 2 * p];  v1 = W[n * HH + 2 * p + 1]; }
    else       { v0 = W[(2 * p) * M + n]; v1 = W[(2 * p + 1) * M + n]; }
    out[idx] = pack_hilo(v0, v1);
}

// ---------------- fused weight packer (W_in, whh0, whh1, W_out) ----------------
__global__ void pack_all4(const float* __restrict__ W_in,
                          const float* __restrict__ whh0, const float* __restrict__ whh1,
                          const float* __restrict__ W_out) {
    int idx = blockIdx.x * blockDim.x + threadIdx.x;
    if (idx < 8192) {                 // W_in: [128][128], trans=0
        int n = idx / HP, p = idx - (idx / HP) * HP;
        g_wpk_in[idx] = pack_hilo(W_in[(2 * p) * HH + n], W_in[(2 * p + 1) * HH + n]);
    } else if (idx < 32768) {         // whh0: [384][128], trans=1
        int li = idx - 8192;
        int n = li / HP, p = li - n * HP;
        g_wpk_h0[li] = pack_hilo(whh0[n * HH + 2 * p], whh0[n * HH + 2 * p + 1]);
    } else if (idx < 57344) {         // whh1
        int li = idx - 32768;
        int n = li / HP, p = li - n * HP;
        g_wpk_h1[li] = pack_hilo(whh1[n * HH + 2 * p], whh1[n * HH + 2 * p + 1]);
    } else if (idx < 61440) {         // W_out: [128][32] -> 64 cols zero-padded, trans=0
        int li = idx - 57344;
        int n = li / HP, p = li - n * HP;
        float v0 = (n < 32) ? W_out[(2 * p) * 32 + n] : 0.0f;
        float v1 = (n < 32) ? W_out[(2 * p + 1) * 32 + n] : 0.0f;
        g_wpk_out[li] = pack_hilo(v0, v1);
    }
}

__global__ void pack_A(const float* __restrict__ A, uint2* __restrict__ out, int rows) {
    int idx = blockIdx.x * blockDim.x + threadIdx.x;
    if (idx >= rows * HP) return;
    int r = idx >> 6;
    int p = idx & 63;
    float2 v = *(const float2*)(A + (size_t)r * HH + 2 * p);
    out[idx] = pack_hilo(v.x, v.y);
}

// ---------------- CSR build ----------------
__global__ void count_deg(const int* __restrict__ dst) {
    int e = blockIdx.x * blockDim.x + threadIdx.x;
    if (e < EE) atomicAdd(&g_deg[dst[e]], 1);
}

__global__ void scan_local() {
    int b = blockIdx.x;
    int i = b * 1024 + threadIdx.x;
    int lane = threadIdx.x & 31, wid = threadIdx.x >> 5;
    int v = (i < NN) ? g_deg[i] : 0;
    int x = v;
    #pragma unroll
    for (int o = 1; o < 32; o <<= 1) {
        int t = __shfl_up_sync(0xffffffffu, x, o);
        if (lane >= o) x += t;
    }
    __shared__ int wsum[32];
    if (lane == 31) wsum[wid] = x;
    __syncthreads();
    if (wid == 0) {
        int y = wsum[lane];
        #pragma unroll
        for (int o = 1; o < 32; o <<= 1) {
            int t = __shfl_up_sync(0xffffffffu, y, o);
            if (lane >= o) y += t;
        }
        wsum[lane] = y;
    }
    __syncthreads();
    int excl = x - v + (wid > 0 ? wsum[wid - 1] : 0);
    if (i < NN) g_off[i] = excl;
    if (threadIdx.x == 1023) g_blk[b] = excl + v;
}

__global__ void scan_blk() {
    if (threadIdx.x == 0) {
        int s = 0;
        for (int i = 0; i < SCAN_BLOCKS; i++) {
            int t = g_blk[i];
            g_blkoff[i] = s;
            s += t;
        }
        g_off[NN] = s;
    }
}

__global__ void scan_add() {
    int i = blockIdx.x * blockDim.x + threadIdx.x;
    if (i < NN) {
        int o = g_off[i] + g_blkoff[i >> 10];
        g_off[i] = o;
        g_cur[i] = o;
    }
}

__global__ void scatter_edges(const int* __restrict__ src, const int* __restrict__ dst) {
    int e = blockIdx.x * blockDim.x + threadIdx.x;
    if (e < EE) {
        int p = atomicAdd(&g_cur[dst[e]], 1);
        g_srcs[p] = src[e];
    }
}

// ---------------- cp.async helper ----------------
__device__ __forceinline__ void cp16(void* smem_dst, const void* gsrc, bool valid) {
    uint32_t saddr = (uint32_t)__cvta_generic_to_shared(smem_dst);
    int sz = valid ? 16 : 0;
    asm volatile("cp.async.cg.shared.global [%0], [%1], 16, %2;\n"
                 :: "r"(saddr), "l"(gsrc), "r"(sz));
}

// ---------------- bf16x2 split-MMA GEMM (tile 128x64, 2 blocks/SM) ----------------
__device__ __forceinline__ void mma_bf16(float* d, const uint32_t* a, const uint32_t* b) {
    asm volatile(
        "mma.sync.aligned.m16n8k16.row.col.f32.bf16.bf16.f32 "
        "{%0,%1,%2,%3}, {%4,%5,%6,%7}, {%8,%9}, {%0,%1,%2,%3};"
        : "+f"(d[0]), "+f"(d[1]), "+f"(d[2]), "+f"(d[3])
        : "r"(a[0]), "r"(a[1]), "r"(a[2]), "r"(a[3]), "r"(b[0]), "r"(b[1]));
}

#define ASTRIDE 68
#define GEMM_SMEM ((128 + 64) * ASTRIDE * 8)

__global__ void __launch_bounds__(256, 2)
bf16x2_gemm(const uint2* __restrict__ Apk, const uint2* __restrict__ Bpk,
            const float* __restrict__ bias, float* __restrict__ C,
            uint2* __restrict__ Cpk, int nrows, int M, int relu) {
    extern __shared__ uint2 sm[];
    uint2* As = sm;
    uint2* Bs = sm + 128 * ASTRIDE;
    int tid  = threadIdx.x;
    int wid  = tid >> 5, lane = tid & 31;
    int gid  = lane >> 2, tg = lane & 3;
    int wm   = (wid & 3) * 32;
    int wn   = (wid >> 2) * 32;
    int r0   = blockIdx.y * 128;
    int n0   = blockIdx.x * 64;
    int ncols = (M < 64) ? M : 64;    // valid columns in this tile (for M=32 projection)

    #pragma unroll
    for (int t = 0; t < 16; t++) {
        int q   = tid + t * 256;
        int row = q >> 5;
        int j   = q & 31;
        bool ok = (r0 + row < nrows);
        cp16(As + row * ASTRIDE + 2 * j,
             Apk + (size_t)(r0 + row) * HP + 2 * j, ok);
    }
    #pragma unroll
    for (int t = 0; t < 8; t++) {
        int q   = tid + t * 256;
        int col = q >> 5;
        int j   = q & 31;
        cp16(Bs + col * ASTRIDE + 2 * j,
             Bpk + (size_t)(n0 + col) * HP + 2 * j, true);
    }
    asm volatile("cp.async.commit_group;\n");
    asm volatile("cp.async.wait_group 0;\n");
    __syncthreads();

    float acc[2][4][4];
    #pragma unroll
    for (int mt = 0; mt < 2; mt++)
        #pragma unroll
        for (int nt = 0; nt < 4; nt++)
            #pragma unroll
            for (int k = 0; k < 4; k++) acc[mt][nt][k] = 0.0f;

    #pragma unroll
    for (int s = 0; s < 8; s++) {
        int p0 = 8 * s;
        uint32_t ah[2][4], al[2][4];
        #pragma unroll
        for (int mt = 0; mt < 2; mt++) {
            int r = wm + mt * 16 + gid;
            uint2 u0 = As[r * ASTRIDE + p0 + tg];
            uint2 u1 = As[(r + 8) * ASTRIDE + p0 + tg];
            uint2 u2 = As[r * ASTRIDE + p0 + tg + 4];
            uint2 u3 = As[(r + 8) * ASTRIDE + p0 + tg + 4];
            ah[mt][0] = u0.x; ah[mt][1] = u1.x; ah[mt][2] = u2.x; ah[mt][3] = u3.x;
            al[mt][0] = u0.y; al[mt][1] = u1.y; al[mt][2] = u2.y; al[mt][3] = u3.y;
        }
        #pragma unroll
        for (int nt = 0; nt < 4; nt++) {
            int c = wn + nt * 8 + gid;
            uint2 v0 = Bs[c * ASTRIDE + p0 + tg];
            uint2 v1 = Bs[c * ASTRIDE + p0 + tg + 4];
            uint32_t bh[2] = { v0.x, v1.x };
            uint32_t bl[2] = { v0.y, v1.y };
            #pragma unroll
            for (int mt = 0; mt < 2; mt++) {
                mma_bf16(acc[mt][nt], ah[mt], bh);
                mma_bf16(acc[mt][nt], al[mt], bh);
                mma_bf16(acc[mt][nt], ah[mt], bl);
            }
        }
    }

    #pragma unroll
    for (int nt = 0; nt < 4; nt++) {
        int c = n0 + wn + nt * 8 + 2 * tg;
        int cl = wn + nt * 8 + 2 * tg;       // column within tile
        bool cok = (cl < ncols);
        float b0 = (bias && cok) ? bias[c] : 0.0f;
        float b1 = (bias && cok) ? bias[c + 1] : 0.0f;
        #pragma unroll
        for (int mt = 0; mt < 2; mt++) {
            int row = r0 + wm + mt * 16 + gid;
            float v0 = acc[mt][nt][0] + b0;
            float v1 = acc[mt][nt][1] + b1;
            float v2 = acc[mt][nt][2] + b0;
            float v3 = acc[mt][nt][3] + b1;
            if (relu) {
                v0 = fmaxf(v0, 0.0f); v1 = fmaxf(v1, 0.0f);
                v2 = fmaxf(v2, 0.0f); v3 = fmaxf(v3, 0.0f);
            }
            if (cok && row < nrows) {
                *(float2*)(C + (size_t)row * M + c) = make_float2(v0, v1);
                if (Cpk) Cpk[(size_t)row * HP + (c >> 1)] = pack_hilo(v0, v1);
            }
            if (cok && row + 8 < nrows) {
                *(float2*)(C + (size_t)(row + 8) * M + c) = make_float2(v2, v3);
                if (Cpk) Cpk[(size_t)(row + 8) * HP + (c >> 1)] = pack_hilo(v2, v3);
            }
        }
    }
}

// ---------------- gather-sum over node features (CSR) -> packed agg ----------------
__global__ void gather_sum(const float* __restrict__ hsrc, uint2* __restrict__ aggpk) {
    int w    = (blockIdx.x * blockDim.x + threadIdx.x) >> 5;
    int lane = threadIdx.x & 31;
    if (w >= NN) return;
    int s0 = g_off[w], s1 = g_off[w + 1];
    float4 acc = make_float4(0.f, 0.f, 0.f, 0.f);
    for (int e = s0; e < s1; e++) {
        int s = g_srcs[e];
        float4 v = *((const float4*)(hsrc + (size_t)s * HH) + lane);
        acc.x += v.x; acc.y += v.y; acc.z += v.z; acc.w += v.w;
    }
    uint2 p0 = pack_hilo(acc.x, acc.y);
    uint2 p1 = pack_hilo(acc.z, acc.w);
    *(uint4*)(aggpk + (size_t)w * HP + 2 * lane) = make_uint4(p0.x, p0.y, p1.x, p1.y);
}

// ---------------- GRU elementwise update ----------------
__device__ __forceinline__ float sigm(float x) { return 1.0f / (1.0f + __expf(-x)); }

__global__ void gru_update(const float* __restrict__ gi, const float* __restrict__ gh,
                           const float* __restrict__ h, float* __restrict__ hout,
                           uint2* __restrict__ pk) {
    int tid = blockIdx.x * blockDim.x + threadIdx.x;
    if (tid >= NN * 32) return;
    int n = tid >> 5;
    int j = tid & 31;
    const float4* gir = (const float4*)(gi + (size_t)n * M3);
    const float4* ghr = (const float4*)(gh + (size_t)n * M3);
    float4 ir  = gir[j],      iz  = gir[32 + j], inn = gir[64 + j];
    float4 hr  = ghr[j],      hz  = ghr[32 + j], hn  = ghr[64 + j];
    float4 hv  = *((const float4*)(h + (size_t)n * HH) + j);
    float4 o;
    {
        float rt = sigm(ir.x + hr.x), zt = sigm(iz.x + hz.x);
        float nt = tanhf(inn.x + rt * hn.x);
        o.x = (1.0f - zt) * nt + zt * hv.x;
    }
    {
        float rt = sigm(ir.y + hr.y), zt = sigm(iz.y + hz.y);
        float nt = tanhf(inn.y + rt * hn.y);
        o.y = (1.0f - zt) * nt + zt * hv.y;
    }
    {
        float rt = sigm(ir.z + hr.z), zt = sigm(iz.z + hz.z);
        float nt = tanhf(inn.z + rt * hn.z);
        o.z = (1.0f - zt) * nt + zt * hv.z;
    }
    {
        float rt = sigm(ir.w + hr.w), zt = sigm(iz.w + hz.w);
        float nt = tanhf(inn.w + rt * hn.w);
        o.w = (1.0f - zt) * nt + zt * hv.w;
    }
    *((float4*)(hout + (size_t)n * HH) + j) = o;
    if (pk) {
        uint2 p0 = pack_hilo(o.x, o.y);
        uint2 p1 = pack_hilo(o.z, o.w);
        *(uint4*)(pk + (size_t)n * HP + 2 * j) = make_uint4(p0.x, p0.y, p1.x, p1.y);
    }
}

// ---------------- cached streams/events (created once, before graph capture) ----------------
static cudaStream_t sCsr = nullptr, s2 = nullptr;
static cudaEvent_t ev0, evCsr, evWc0, evWc1, evH0, evGh0, evH1, evGh1;
static bool g_res_init = false;

static void init_resources_once() {
    if (g_res_init) return;
    cudaStreamCreateWithFlags(&sCsr, cudaStreamNonBlocking);
    cudaStreamCreateWithFlags(&s2,   cudaStreamNonBlocking);
    cudaEventCreateWithFlags(&ev0,   cudaEventDisableTiming);
    cudaEventCreateWithFlags(&evCsr, cudaEventDisableTiming);
    cudaEventCreateWithFlags(&evWc0, cudaEventDisableTiming);
    cudaEventCreateWithFlags(&evWc1, cudaEventDisableTiming);
    cudaEventCreateWithFlags(&evH0,  cudaEventDisableTiming);
    cudaEventCreateWithFlags(&evGh0, cudaEventDisableTiming);
    cudaEventCreateWithFlags(&evH1,  cudaEventDisableTiming);
    cudaEventCreateWithFlags(&evGh1, cudaEventDisableTiming);
    g_res_init = true;
}

// ---------------- launch (forked-stream graph) ----------------
extern "C" void kernel_launch(void* const* d_in, const int* in_sizes, int n_in,
                              void* d_out, int out_size) {
    const float* x      = (const float*)d_in[0];
    const int*   ei     = (const int*)  d_in[1];
    const float* W_in   = (const float*)d_in[2];
    const float* b_in   = (const float*)d_in[3];
    const float* W_msg0 = (const float*)d_in[4];
    const float* wih0   = (const float*)d_in[5];
    const float* whh0   = (const float*)d_in[6];
    const float* bih0   = (const float*)d_in[7];
    const float* bhh0   = (const float*)d_in[8];
    const float* W_msg1 = (const float*)d_in[9];
    const float* wih1   = (const float*)d_in[10];
    const float* whh1   = (const float*)d_in[11];
    const float* bih1   = (const float*)d_in[12];
    const float* bhh1   = (const float*)d_in[13];
    const float* W_out  = (const float*)d_in[14];
    const float* b_out  = (const float*)d_in[15];
    float* out = (float*)d_out;

    const int* src = ei;
    const int* dst = ei + EE;

    float *h, *h2, *gi, *gh, *wcf0, *wcf1;
    uint2 *xpk, *hpk, *aggpk, *win, *wc0, *wc1, *wh0, *wh1, *wout;
    int* deg;
    cudaGetSymbolAddress((void**)&h,     g_h);
    cudaGetSymbolAddress((void**)&h2,    g_h2);
    cudaGetSymbolAddress((void**)&gi,    g_gi);
    cudaGetSymbolAddress((void**)&gh,    g_gh);
    cudaGetSymbolAddress((void**)&wcf0,  g_wcf0);
    cudaGetSymbolAddress((void**)&wcf1,  g_wcf1);
    cudaGetSymbolAddress((void**)&xpk,   g_xpk);
    cudaGetSymbolAddress((void**)&hpk,   g_hpk);
    cudaGetSymbolAddress((void**)&aggpk, g_aggpk);
    cudaGetSymbolAddress((void**)&win,   g_wpk_in);
    cudaGetSymbolAddress((void**)&wc0,   g_wpk_c0);
    cudaGetSymbolAddress((void**)&wc1,   g_wpk_c1);
    cudaGetSymbolAddress((void**)&wh0,   g_wpk_h0);
    cudaGetSymbolAddress((void**)&wh1,   g_wpk_h1);
    cudaGetSymbolAddress((void**)&wout,  g_wpk_out);
    cudaGetSymbolAddress((void**)&deg,   g_deg);

    cudaFuncSetAttribute(bf16x2_gemm, cudaFuncAttributeMaxDynamicSharedMemorySize, GEMM_SMEM);

    init_resources_once();

    int rb = (NN + 127) / 128;
    int gthreads = NN * 32;

    // ---- main stream first (so a big GEMM lands in ncu's profiled slot) ----
    pack_all4<<<(61440 + 255) / 256, 256>>>(W_in, whh0, whh1, W_out);     // launch 1
    pack_A<<<(NN * HP + 255) / 256, 256>>>(x, xpk, NN);                   // launch 2
    bf16x2_gemm<<<dim3(2, rb), 256, GEMM_SMEM>>>(xpk, win, b_in, h, hpk, NN, HH, 1); // 3
    cudaEventRecord(ev0, 0);
    cudaEventRecord(evH0, 0);

    // ---- sCsr: Wc0 prep then CSR build ----
    cudaStreamWaitEvent(sCsr, ev0, 0);
    wc_compute<<<(HH * M3 + 255) / 256, 256, 0, sCsr>>>(W_msg0, wih0, wcf0);      // 4
    pack_B<<<(M3 * HP + 255) / 256, 256, 0, sCsr>>>(wcf0, wc0, M3, 0);            // 5
    cudaEventRecord(evWc0, sCsr);

    // ---- s2: gh0 (slot 6 — the 2346-block GEMM we want profiled) ----
    cudaStreamWaitEvent(s2, evH0, 0);
    bf16x2_gemm<<<dim3(6, rb), 256, GEMM_SMEM, s2>>>(hpk, wh0, bhh0, gh, nullptr, NN, M3, 0); // 6
    cudaEventRecord(evGh0, s2);

    // ---- sCsr: rest of prep (CSR + Wc1) ----
    cudaMemsetAsync(deg, 0, NN * sizeof(int), sCsr);
    count_deg<<<(EE + 255) / 256, 256, 0, sCsr>>>(dst);
    scan_local<<<SCAN_BLOCKS, 1024, 0, sCsr>>>();
    scan_blk<<<1, 32, 0, sCsr>>>();
    scan_add<<<SCAN_BLOCKS, 1024, 0, sCsr>>>();
    scatter_edges<<<(EE + 255) / 256, 256, 0, sCsr>>>(src, dst);
    cudaEventRecord(evCsr, sCsr);
    wc_compute<<<(HH * M3 + 255) / 256, 256, 0, sCsr>>>(W_msg1, wih1, wcf1);
    pack_B<<<(M3 * HP + 255) / 256, 256, 0, sCsr>>>(wcf1, wc1, M3, 0);
    cudaEventRecord(evWc1, sCsr);

    // ---- layer 0 main path ----
    cudaStreamWaitEvent(0, evCsr, 0);
    gather_sum<<<(gthreads + 255) / 256, 256>>>(h, aggpk);
    cudaStreamWaitEvent(0, evWc0, 0);
    bf16x2_gemm<<<dim3(6, rb), 256, GEMM_SMEM>>>(aggpk, wc0, bih0, gi, nullptr, NN, M3, 0);
    cudaStreamWaitEvent(0, evGh0, 0);
    gru_update<<<(gthreads + 255) / 256, 256>>>(gi, gh, h, h2, hpk);
    cudaEventRecord(evH1, 0);

    // ---- layer 1: gh on s2, gather->gi on main ----
    cudaStreamWaitEvent(s2, evH1, 0);
    bf16x2_gemm<<<dim3(6, rb), 256, GEMM_SMEM, s2>>>(hpk, wh1, bhh1, gh, nullptr, NN, M3, 0);
    cudaEventRecord(evGh1, s2);

    gather_sum<<<(gthreads + 255) / 256, 256>>>(h2, aggpk);
    cudaStreamWaitEvent(0, evWc1, 0);
    bf16x2_gemm<<<dim3(6, rb), 256, GEMM_SMEM>>>(aggpk, wc1, bih1, gi, nullptr, NN, M3, 0);
    cudaStreamWaitEvent(0, evGh1, 0);
    gru_update<<<(gthreads + 255) / 256, 256>>>(gi, gh, h2, h, hpk);

    // out = h @ W_out + b_out  (tensor path, M=32 with padded 64-col B tile)
    bf16x2_gemm<<<dim3(1, rb), 256, GEMM_SMEM>>>(hpk, wout, b_out, out, nullptr, NN, 32, 0);
}